// round 9
// baseline (speedup 1.0000x reference)
#include <cuda_runtime.h>
#include <cuda_bf16.h>

// Shapes: pred_logits [16,32,1024,80] (UNUSED), pred_logits_b [16,32,1024,2],
//         pred_boxes [16,32,1024,4], tgt_bbox [16,32,1,4], tgt_ids [512] (UNUSED)
// Output (f32, concatenated): C [512*1024], rows [512], mode_idx [1]

#define NQ  1024
#define NF  512
#define C_SIZE (NF * NQ)
#define TPB 256               // 4 consecutive queries per thread, 1 CTA per frame

__device__ __align__(16) int g_cnt[NQ];   // zero-init; bincount of selected rows
__device__ unsigned int      g_done;      // zero-init completion counter

// Monotone float -> uint mapping: a < b  <=>  enc(a) < enc(b)
__device__ __forceinline__ unsigned int float_to_ordered(float f) {
    unsigned int u = __float_as_uint(f);
    return (u & 0x80000000u) ? ~u : (u | 0x80000000u);
}

__global__ void __launch_bounds__(TPB, 4)
fused_kernel(const float* __restrict__ logits_b,
             const float* __restrict__ boxes,
             const float* __restrict__ tgt,
             float* __restrict__ out)
{
    const int f    = blockIdx.x;   // frame 0..511
    const int tid  = threadIdx.x;  // 0..255
    const int lane = tid & 31;
    const int wid  = tid >> 5;     // 0..7

    // Target box (cxcywh -> xyxy)
    const float4 tb = reinterpret_cast<const float4*>(tgt)[f];
    const float tx1 = tb.x - 0.5f * tb.z;
    const float ty1 = tb.y - 0.5f * tb.w;
    const float tx2 = tb.x + 0.5f * tb.z;
    const float ty2 = tb.y + 0.5f * tb.w;
    const float area2 = (tx2 - tx1) * (ty2 - ty1);

    const float4* __restrict__ bptr = reinterpret_cast<const float4*>(boxes)    + (size_t)f * NQ;
    const float4* __restrict__ lptr = reinterpret_cast<const float4*>(logits_b) + (size_t)f * (NQ / 2);
    float4* __restrict__ cptr = reinterpret_cast<float4*>(out + (size_t)f * NQ);

    // Thread t handles queries 4t..4t+3: 6 front-batched streaming loads (MLP=6)
    const int q0 = tid * 4;
    float4 p[4];
    p[0] = __ldcs(&bptr[q0 + 0]);
    p[1] = __ldcs(&bptr[q0 + 1]);
    p[2] = __ldcs(&bptr[q0 + 2]);
    p[3] = __ldcs(&bptr[q0 + 3]);
    const float4 la = __ldcs(&lptr[tid * 2 + 0]);   // (l0.x,l0.y,l1.x,l1.y)
    const float4 lb = __ldcs(&lptr[tid * 2 + 1]);   // (l2.x,l2.y,l3.x,l3.y)

    const float ld_[4][2] = { {la.x, la.y}, {la.z, la.w}, {lb.x, lb.y}, {lb.z, lb.w} };

    float cres[4];
    unsigned int obest = 0xFFFFFFFFu;
    int          bestq = 0;

    #pragma unroll
    for (int i = 0; i < 4; i++) {
        const int q = q0 + i;

        const float cost_bbox = fabsf(p[i].x - tb.x) + fabsf(p[i].y - tb.y)
                              + fabsf(p[i].z - tb.z) + fabsf(p[i].w - tb.w);

        const float x1 = p[i].x - 0.5f * p[i].z;
        const float y1 = p[i].y - 0.5f * p[i].w;
        const float x2 = p[i].x + 0.5f * p[i].z;
        const float y2 = p[i].y + 0.5f * p[i].w;
        const float area1 = (x2 - x1) * (y2 - y1);

        const float lt_x = fmaxf(x1, tx1), lt_y = fmaxf(y1, ty1);
        const float rb_x = fminf(x2, tx2), rb_y = fminf(y2, ty2);
        const float iw = fmaxf(rb_x - lt_x, 0.0f);
        const float ih = fmaxf(rb_y - lt_y, 0.0f);
        const float inter = iw * ih;
        const float uni   = area1 + area2 - inter;

        const float cx1 = fminf(x1, tx1), cy1 = fminf(y1, ty1);
        const float cx2 = fmaxf(x2, tx2), cy2 = fmaxf(y2, ty2);
        const float cw = fmaxf(cx2 - cx1, 0.0f);
        const float ch = fmaxf(cy2 - cy1, 0.0f);
        const float areac = cw * ch;

        // giou = inter/uni - (areac-uni)/areac, combined into ONE fast division:
        //   giou = (inter*areac - (areac-uni)*uni) / (uni*areac)
        const float giou_num = inter * areac - (areac - uni) * uni;
        const float giou     = __fdividef(giou_num, uni * areac);

        // -softmax[1] == -1/(1+exp(l0-l1)) : one EX2 + one RCP
        const float cost_class = -__fdividef(1.0f, 1.0f + __expf(ld_[i][0] - ld_[i][1]));

        const float c = 5.0f * cost_bbox + cost_class - 2.0f * giou;
        cres[i] = c;

        const unsigned int oc = float_to_ordered(c);
        if (oc < obest) { obest = oc; bestq = q; }   // q increasing -> first-min kept
    }

    // Streaming store: C is write-once, never re-read by this kernel
    __stcs(&cptr[tid], make_float4(cres[0], cres[1], cres[2], cres[3]));

    // Warp argmin: min cost, then min q among cost-ties (exact JAX tie-break)
    const unsigned int wmin = __reduce_min_sync(0xFFFFFFFFu, obest);
    const unsigned int qc   = (obest == wmin) ? (unsigned int)bestq : 0xFFFFFFFFu;
    const unsigned int wq   = __reduce_min_sync(0xFFFFFFFFu, qc);

    __shared__ unsigned long long warp_min[TPB / 32];
    if (lane == 0)
        warp_min[wid] = ((unsigned long long)wmin << 32) | wq;
    __syncthreads();

    if (wid != 0) return;   // warps 1..7 retire immediately (no barrier on atomics)

    int islast = 0;
    if (lane == 0) {
        unsigned long long m = warp_min[0];
        #pragma unroll
        for (int w = 1; w < TPB / 32; w++)
            if (warp_min[w] < m) m = warp_min[w];
        const int q = (int)(m & 0xFFFFFFFFu);
        out[C_SIZE + f] = (float)q;      // rows output

        // Bincount contribution, then release-increment completion counter.
        atomicAdd(&g_cnt[q], 1);
        unsigned int v;
        asm volatile("atom.acq_rel.gpu.global.add.u32 %0, [%1], %2;"
                     : "=r"(v) : "l"(&g_done), "r"(1u) : "memory");
        islast = (v == NF - 1) ? 1 : 0;
    }
    islast = __shfl_sync(0xFFFFFFFFu, islast, 0);

    // ---- Last CTA's warp 0: mode = argmax(bincount), min-idx tie-break ----
    if (islast) {
        const int4* cnt4 = reinterpret_cast<const int4*>(g_cnt);
        int mykey = 0;
        #pragma unroll
        for (int i = 0; i < 8; i++) {            // 32 lanes x 8 int4 = 1024 bins
            const int idx = i * 32 + lane;
            int4 cv;
            asm volatile("ld.relaxed.gpu.global.v4.s32 {%0,%1,%2,%3}, [%4];"
                         : "=r"(cv.x), "=r"(cv.y), "=r"(cv.z), "=r"(cv.w)
                         : "l"(&cnt4[idx]) : "memory");
            const int bin = idx * 4;
            const int k0 = (cv.x << 10) | (NQ - 1 - bin);
            const int k1 = (cv.y << 10) | (NQ - 2 - bin);
            const int k2 = (cv.z << 10) | (NQ - 3 - bin);
            const int k3 = (cv.w << 10) | (NQ - 4 - bin);
            mykey = max(mykey, max(max(k0, k1), max(k2, k3)));
        }
        const int wmax = (int)__reduce_max_sync(0xFFFFFFFFu, (unsigned int)mykey);
        if (lane == 0) {
            out[C_SIZE + NF] = (float)((NQ - 1) - (wmax & (NQ - 1)));
            asm volatile("st.relaxed.gpu.global.u32 [%0], %1;"
                         :: "l"(&g_done), "r"(0u) : "memory");
        }
        // re-zero g_cnt for the next graph replay
        int4* cnt4w = reinterpret_cast<int4*>(g_cnt);
        const int4 z = make_int4(0, 0, 0, 0);
        #pragma unroll
        for (int i = 0; i < 8; i++)
            cnt4w[i * 32 + lane] = z;
    }
}

extern "C" void kernel_launch(void* const* d_in, const int* in_sizes, int n_in,
                              void* d_out, int out_size)
{
    // metadata order: pred_logits, pred_logits_b, pred_boxes, tgt_bbox, tgt_ids
    const float* logits_b = (const float*)d_in[1];
    const float* boxes    = (const float*)d_in[2];
    const float* tgt      = (const float*)d_in[3];
    float* out = (float*)d_out;

    fused_kernel<<<NF, TPB>>>(logits_b, boxes, tgt, out);
}

// round 10
// speedup vs baseline: 1.0370x; 1.0370x over previous
#include <cuda_runtime.h>
#include <cuda_bf16.h>

// Shapes: pred_logits [16,32,1024,80] (UNUSED), pred_logits_b [16,32,1024,2],
//         pred_boxes [16,32,1024,4], tgt_bbox [16,32,1,4], tgt_ids [512] (UNUSED)
// Output (f32, concatenated): C [512*1024], rows [512], mode_idx [1]

#define NQ  1024
#define NF  512
#define C_SIZE (NF * NQ)
#define TPB 256               // 8 warps; warp w owns queries [128w, 128w+128)

__device__ __align__(16) int g_cnt[NQ];   // zero-init; bincount of selected rows
__device__ unsigned int      g_done;      // zero-init completion counter

// Monotone float -> uint mapping: a < b  <=>  enc(a) < enc(b)
__device__ __forceinline__ unsigned int float_to_ordered(float f) {
    unsigned int u = __float_as_uint(f);
    return (u & 0x80000000u) ? ~u : (u | 0x80000000u);
}

__global__ void __launch_bounds__(TPB, 4)
fused_kernel(const float* __restrict__ logits_b,
             const float* __restrict__ boxes,
             const float* __restrict__ tgt,
             float* __restrict__ out)
{
    const int f    = blockIdx.x;   // frame 0..511
    const int tid  = threadIdx.x;  // 0..255
    const int lane = tid & 31;
    const int wid  = tid >> 5;     // 0..7

    // Target box (cxcywh -> xyxy)
    const float4 tb = reinterpret_cast<const float4*>(tgt)[f];
    const float tx1 = tb.x - 0.5f * tb.z;
    const float ty1 = tb.y - 0.5f * tb.w;
    const float tx2 = tb.x + 0.5f * tb.z;
    const float ty2 = tb.y + 0.5f * tb.w;
    const float area2 = (tx2 - tx1) * (ty2 - ty1);

    const float4* __restrict__ bptr = reinterpret_cast<const float4*>(boxes)    + (size_t)f * NQ;
    const float2* __restrict__ lptr = reinterpret_cast<const float2*>(logits_b) + (size_t)f * NQ;
    float* __restrict__ cptr = out + (size_t)f * NQ;

    // Lane-coalesced layout: q = wid*128 + i*32 + lane
    //   box load: LDG.128, 32 consecutive lanes -> 4 lines (coalesced)
    //   logit load: LDG.64, 32 consecutive lanes -> 2 lines (coalesced)
    const int qbase = wid * 128 + lane;
    float4 p[4];
    float2 l[4];
    #pragma unroll
    for (int i = 0; i < 4; i++) {
        p[i] = bptr[qbase + i * 32];
        l[i] = lptr[qbase + i * 32];
    }

    unsigned int obest = 0xFFFFFFFFu;
    int          bestq = 0;

    #pragma unroll
    for (int i = 0; i < 4; i++) {
        const int q = qbase + i * 32;

        const float cost_bbox = fabsf(p[i].x - tb.x) + fabsf(p[i].y - tb.y)
                              + fabsf(p[i].z - tb.z) + fabsf(p[i].w - tb.w);

        const float x1 = p[i].x - 0.5f * p[i].z;
        const float y1 = p[i].y - 0.5f * p[i].w;
        const float x2 = p[i].x + 0.5f * p[i].z;
        const float y2 = p[i].y + 0.5f * p[i].w;
        const float area1 = (x2 - x1) * (y2 - y1);

        const float lt_x = fmaxf(x1, tx1), lt_y = fmaxf(y1, ty1);
        const float rb_x = fminf(x2, tx2), rb_y = fminf(y2, ty2);
        const float iw = fmaxf(rb_x - lt_x, 0.0f);
        const float ih = fmaxf(rb_y - lt_y, 0.0f);
        const float inter = iw * ih;
        const float uni   = area1 + area2 - inter;

        const float cx1 = fminf(x1, tx1), cy1 = fminf(y1, ty1);
        const float cx2 = fmaxf(x2, tx2), cy2 = fmaxf(y2, ty2);
        const float cw = fmaxf(cx2 - cx1, 0.0f);
        const float ch = fmaxf(cy2 - cy1, 0.0f);
        const float areac = cw * ch;

        // giou = inter/uni - (areac-uni)/areac  ==  one fast division:
        const float giou_num = inter * areac - (areac - uni) * uni;
        const float giou     = __fdividef(giou_num, uni * areac);

        // -softmax[1] == -1/(1+exp(l0-l1))
        const float cost_class = -__fdividef(1.0f, 1.0f + __expf(l[i].x - l[i].y));

        const float c = 5.0f * cost_bbox + cost_class - 2.0f * giou;
        cptr[q] = c;                               // coalesced STG.32

        const unsigned int oc = float_to_ordered(c);
        if (oc < obest) { obest = oc; bestq = q; } // q increasing per thread
    }

    // Warp argmin: min cost, then min q among cost-ties (exact JAX tie-break)
    const unsigned int wmin = __reduce_min_sync(0xFFFFFFFFu, obest);
    const unsigned int qc   = (obest == wmin) ? (unsigned int)bestq : 0xFFFFFFFFu;
    const unsigned int wq   = __reduce_min_sync(0xFFFFFFFFu, qc);

    __shared__ unsigned long long warp_min[TPB / 32];
    if (lane == 0)
        warp_min[wid] = ((unsigned long long)wmin << 32) | wq;
    __syncthreads();

    if (wid != 0) return;      // warps 1..7 retire

    if (lane == 0) {
        unsigned long long m = warp_min[0];
        #pragma unroll
        for (int w = 1; w < TPB / 32; w++)
            if (warp_min[w] < m) m = warp_min[w];
        const int q = (int)(m & 0xFFFFFFFFu);
        out[C_SIZE + f] = (float)q;      // rows output

        // FIRE-AND-FORGET publishes: no return value, no wait, no serialization
        // on the critical path. REDG drains in L2 at ~0.85 cyc/op.
        asm volatile("red.relaxed.gpu.global.add.u32 [%0], %1;"
                     :: "l"((unsigned int*)&g_cnt[q]), "r"(1u) : "memory");
        asm volatile("red.release.gpu.global.add.u32 [%0], %1;"
                     :: "l"(&g_done), "r"(1u) : "memory");
    }

    // ---- Dedicated waiter: block 0's warp 0 detects completion, computes mode ----
    if (f == 0) {
        // spin until all NF CTAs have released their increments
        int done = 0;
        do {
            unsigned int v = 0;
            if (lane == 0) {
                asm volatile("ld.acquire.gpu.global.u32 %0, [%1];"
                             : "=r"(v) : "l"(&g_done) : "memory");
            }
            done = (__shfl_sync(0xFFFFFFFFu, v, 0) == NF);
            if (!done) __nanosleep(64);
        } while (!done);

        // mode = argmax(bincount) with smallest-index tie-break
        const int4* cnt4 = reinterpret_cast<const int4*>(g_cnt);
        int mykey = 0;
        #pragma unroll
        for (int i = 0; i < 8; i++) {            // 32 lanes x 8 int4 = 1024 bins
            const int idx = i * 32 + lane;
            int4 cv;
            asm volatile("ld.relaxed.gpu.global.v4.s32 {%0,%1,%2,%3}, [%4];"
                         : "=r"(cv.x), "=r"(cv.y), "=r"(cv.z), "=r"(cv.w)
                         : "l"(&cnt4[idx]) : "memory");
            const int bin = idx * 4;
            const int k0 = (cv.x << 10) | (NQ - 1 - bin);
            const int k1 = (cv.y << 10) | (NQ - 2 - bin);
            const int k2 = (cv.z << 10) | (NQ - 3 - bin);
            const int k3 = (cv.w << 10) | (NQ - 4 - bin);
            mykey = max(mykey, max(max(k0, k1), max(k2, k3)));
        }
        const int wmax = (int)__reduce_max_sync(0xFFFFFFFFu, (unsigned int)mykey);
        if (lane == 0) {
            out[C_SIZE + NF] = (float)((NQ - 1) - (wmax & (NQ - 1)));
            asm volatile("st.relaxed.gpu.global.u32 [%0], %1;"
                         :: "l"(&g_done), "r"(0u) : "memory");
        }
        // re-zero g_cnt for the next graph replay
        int4* cnt4w = reinterpret_cast<int4*>(g_cnt);
        const int4 z = make_int4(0, 0, 0, 0);
        #pragma unroll
        for (int i = 0; i < 8; i++)
            cnt4w[i * 32 + lane] = z;
    }
}

extern "C" void kernel_launch(void* const* d_in, const int* in_sizes, int n_in,
                              void* d_out, int out_size)
{
    // metadata order: pred_logits, pred_logits_b, pred_boxes, tgt_bbox, tgt_ids
    const float* logits_b = (const float*)d_in[1];
    const float* boxes    = (const float*)d_in[2];
    const float* tgt      = (const float*)d_in[3];
    float* out = (float*)d_out;

    fused_kernel<<<NF, TPB>>>(logits_b, boxes, tgt, out);
}